// round 15
// baseline (speedup 1.0000x reference)
#include <cuda_runtime.h>
#include <math.h>

// Problem constants (fixed shapes from setup_inputs)
#define BB   2
#define DD   128
#define HH   128
#define WW   128
#define IMG_ELEMS (BB*DD*HH*WW*4)    // 16777216
#define VOX       (BB*DD*HH*WW)      // 4194304

__device__ float g_Ehi[128 * 4];
__device__ float g_Elo[128 * 4];

// ---------------- double-float (two-float) arithmetic -----------------
struct df { float h, l; };

__device__ __forceinline__ df qts(float a, float b) {
    float s = a + b;
    return { s, b - (s - a) };
}
__device__ __forceinline__ df two_sum(float a, float b) {
    float s = a + b;
    float t = s - a;
    return { s, (a - (s - t)) + (b - t) };
}
__device__ __forceinline__ df two_prod(float a, float b) {
    float p = a * b;
    return { p, fmaf(a, b, -p) };
}
__device__ __forceinline__ df df_mul(df a, df b) {
    df p = two_prod(a.h, b.h);
    p.l = p.l + (a.h * b.l + a.l * b.h);
    return qts(p.h, p.l);
}
__device__ __forceinline__ df df_mul_f(df a, float b) {
    df p = two_prod(a.h, b);
    p.l = p.l + a.l * b;
    return qts(p.h, p.l);
}
__device__ __forceinline__ df df_add(df a, df b) {
    df s = two_sum(a.h, b.h);
    s.l = s.l + (a.l + b.l);
    return qts(s.h, s.l);
}
// -----------------------------------------------------------------------

// Cephes/Eigen-style vectorized expf (XLA:CPU) — VALIDATED, do not touch.
__device__ float cephes_expf(float x) {
    const float LOG2EF = 1.44269504088896341f;
    const float C1 = 0.693359375f;
    const float C2 = -2.12194440e-4f;
    float m = floorf(fmaf(x, LOG2EF, 0.5f));
    float r = fmaf(m, -C1, x);
    r = fmaf(m, -C2, r);
    float r2 = __fmul_rn(r, r);
    float y = 1.9875691500E-4f;
    y = fmaf(y, r, 1.3981999507E-3f);
    y = fmaf(y, r, 8.3334519073E-3f);
    y = fmaf(y, r, 4.1665795894E-2f);
    y = fmaf(y, r, 1.6666665459E-1f);
    y = fmaf(y, r, 5.0000001201E-1f);
    y = fmaf(y, r2, r);
    y = __fadd_rn(y, 1.0f);
    return ldexpf(y, (int)m);
}

// fp32 Keys cubic weight with separate roundings per op — VALIDATED.
__device__ float keys_f32_strict(float x) {
    float t1 = __fmul_rn(1.5f, x);
    float t2 = __fsub_rn(t1, 2.5f);
    float t3 = __fmul_rn(t2, x);
    float t4 = __fmul_rn(t3, x);
    float out = __fadd_rn(t4, 1.0f);
    if (x >= 1.0f) {
        float u1 = __fmul_rn(-0.5f, x);
        float u2 = __fadd_rn(u1, 2.5f);
        float u3 = __fmul_rn(u2, x);
        float u4 = __fsub_rn(u3, 4.0f);
        float u5 = __fmul_rn(u4, x);
        out = __fadd_rn(u5, 2.0f);
    }
    if (x >= 2.0f) out = 0.0f;
    return out;
}

// Every product and accumulation order IDENTICAL to validated version.
__global__ void precompute_E_kernel() {
    __shared__ float s_taps[16];
    __shared__ float s_Wn[128 * 4];

    int tid = threadIdx.x;
    if (tid >= 512) return;
    int p = tid >> 2, c = tid & 3;

    if (tid < 16) {
        float kf[16];
        float ksum = 0.0f;
        #pragma unroll
        for (int j = 0; j < 16; ++j) {
            float off = (float)(j - 7);
            float sq = __fmul_rn(off, off);
            float arg = -__fdiv_rn(sq, 12.5f);
            kf[j] = cephes_expf(arg);
            ksum = __fadd_rn(ksum, kf[j]);
        }
        s_taps[tid] = __fdiv_rn(kf[tid], ksum);
    }

    {
        float sf = __fsub_rn(__fmul_rn(__fadd_rn((float)p, 0.5f), 0.03125f), 0.5f);
        float wc[4];
        float ssum = 0.0f;
        #pragma unroll
        for (int cc = 0; cc < 4; ++cc) {
            float x = fabsf(__fsub_rn(sf, (float)cc));
            wc[cc] = keys_f32_strict(x);
            ssum = __fadd_rn(ssum, wc[cc]);
        }
        s_Wn[p * 4 + c] = __fdiv_rn(wc[c], ssum);
    }
    __syncthreads();

    double E = 0.0;
    #pragma unroll
    for (int j = 0; j < 16; ++j) {
        int q = p - 7 + j;
        if (q < 0 || q >= 128) continue;
        E += (double)s_taps[j] * (double)s_Wn[q * 4 + c];
    }
    float hi = (float)E;
    g_Ehi[p * 4 + c] = hi;
    g_Elo[p * 4 + c] = (float)(E - (double)hi);
}

__device__ __forceinline__ int clamp127(int v) {
    return min(max(v, 0), 127);
}

// Compensated (Dot2-style) 4-term df·df dot product — VALIDATED.
__device__ __forceinline__ float dot2_4(
    float eh0, float el0, df u0,
    float eh1, float el1, df u1,
    float eh2, float el2, df u2,
    float eh3, float el3, df u3)
{
    float s = __fmul_rn(eh0, u0.h);
    float c = fmaf(eh0, u0.h, -s);
    c = fmaf(eh0, u0.l, c);
    c = fmaf(el0, u0.h, c);
    #define DOT2_TERM(EH, EL, U)                         \
    {                                                    \
        float p_ = __fmul_rn(EH, (U).h);                 \
        float e_ = fmaf(EH, (U).h, -p_);                 \
        e_ = fmaf(EH, (U).l, e_);                        \
        e_ = fmaf(EL, (U).h, e_);                        \
        float t_ = s + p_;                               \
        float z_ = t_ - s;                               \
        float err_ = (s - (t_ - z_)) + (p_ - z_);        \
        s = t_;                                          \
        c = c + (e_ + err_);                             \
    }
    DOT2_TERM(eh1, el1, u1)
    DOT2_TERM(eh2, el2, u2)
    DOT2_TERM(eh3, el3, u3)
    #undef DOT2_TERM
    return s + c;
}

// Collapse one w-half of the trilinear stencil to a weighted float4 partial.
__device__ __forceinline__ float4 gather_half(
    const float4* __restrict__ img4, int half,
    float wd, float wh, float ww)
{
    float fld = floorf(wd), flh = floorf(wh), flw = floorf(ww);
    float td = wd - fld, th = wh - flh, tw = ww - flw;
    int i0d = (int)fld, i0h = (int)flh, i0w = (int)flw;
    unsigned d0 = (unsigned)clamp127(i0d), d1 = (unsigned)clamp127(i0d + 1);
    unsigned h0 = (unsigned)clamp127(i0h), h1 = (unsigned)clamp127(i0h + 1);
    unsigned wc = (unsigned)clamp127(i0w + half);
    float wwgt = half ? tw : (1.0f - tw);

    float4 c00 = img4[(d0 << 14) + (h0 << 7) + wc];
    float4 c01 = img4[(d0 << 14) + (h1 << 7) + wc];
    float4 c10 = img4[(d1 << 14) + (h0 << 7) + wc];
    float4 c11 = img4[(d1 << 14) + (h1 << 7) + wc];

    float omh = 1.0f - th, omd = 1.0f - td;
    float4 out;
    float a, bb;
    a = c00.x * omh + c01.x * th; bb = c10.x * omh + c11.x * th;
    out.x = (a * omd + bb * td) * wwgt;
    a = c00.y * omh + c01.y * th; bb = c10.y * omh + c11.y * th;
    out.y = (a * omd + bb * td) * wwgt;
    a = c00.z * omh + c01.z * th; bb = c10.z * omh + c11.z * th;
    out.z = (a * omd + bb * td) * wwgt;
    a = c00.w * omh + c01.w * th; bb = c10.w * omh + c11.w * th;
    out.w = (a * omd + bb * td) * wwgt;
    return out;
}

// Block = (b, d, h8): processes rows h = 8*h8 .. 8*h8+7.
__global__ void __launch_bounds__(128) deform_kernel(
    const float* __restrict__ img,     // [B,128,128,128,4]
    const float* __restrict__ coarse,  // [B,4,4,4,3]
    const int*   __restrict__ lbl,     // [B,128,128,128]
    float*       __restrict__ out)     // [IMG_ELEMS] image then [VOX] label
{
    __shared__ float  s_coarse[192];
    __shared__ df     s_prod[8 * 16];   // [row][k]
    __shared__ df     s_U[8 * 12];      // [row][cw*3+comp]

    int bid = blockIdx.x;
    int h8 = bid & 15;
    int d  = (bid >> 4) & 127;
    int b  = bid >> 11;
    int t  = threadIdx.x;
    int hbase = h8 << 3;

    for (int i = t; i < 192; i += 128) s_coarse[i] = coarse[b * 192 + i];
    __syncthreads();

    {   // all 128 threads: one (row, k) pair each
        int r  = t >> 4;
        int k  = t & 15;
        int cd = k >> 2, ch = k & 3;
        int h  = hbase + r;
        df Ed = { g_Ehi[d * 4 + cd], g_Elo[d * 4 + cd] };
        df Eh = { g_Ehi[h * 4 + ch], g_Elo[h * 4 + ch] };
        s_prod[t] = df_mul(Ed, Eh);
    }
    __syncthreads();

    if (t < 96) {
        int r  = t / 12;
        int u  = t - r * 12;
        int cw = u / 3, comp = u - cw * 3;
        df acc = { 0.f, 0.f };
        #pragma unroll
        for (int k = 0; k < 16; ++k)
            acc = df_add(acc, df_mul_f(s_prod[r * 16 + k],
                                       s_coarse[(k * 4 + cw) * 3 + comp]));
        s_U[r * 12 + u] = acc;
    }
    __syncthreads();

    // E row for w = t: loaded ONCE for all 8 rows.
    const float4 ehi = *reinterpret_cast<const float4*>(&g_Ehi[t * 4]);
    const float4 elo = *reinterpret_cast<const float4*>(&g_Elo[t * 4]);

    // per-batch base pointers
    const float4* __restrict__ img4  = reinterpret_cast<const float4*>(img) + (long)b * (128 * 128 * 128);
    const int*    __restrict__ lblb  = lbl + (long)b * (128 * 128 * 128);
    float4*       __restrict__ outi4 = reinterpret_cast<float4*>(out) + (long)b * (128 * 128 * 128);
    float*        __restrict__ outl  = out + IMG_ELEMS + (long)b * (128 * 128 * 128);

    int lane  = t & 31;
    int p     = lane >> 1;
    int half  = lane & 1;
    int wbase = t & ~31;
    int vA    = wbase + p;
    int vB    = wbase + 16 + p;
    const unsigned FULL = 0xffffffffu;

    #pragma unroll
    for (int r = 0; r < 8; ++r) {
        int h = hbase + r;
        const df* sU = &s_U[r * 12];

        // flow for w = t — identical math/order to validated rounds
        float f0 = dot2_4(ehi.x, elo.x, sU[0], ehi.y, elo.y, sU[3],
                          ehi.z, elo.z, sU[6], ehi.w, elo.w, sU[9]);
        float f1 = dot2_4(ehi.x, elo.x, sU[1], ehi.y, elo.y, sU[4],
                          ehi.z, elo.z, sU[7], ehi.w, elo.w, sU[10]);
        float f2 = dot2_4(ehi.x, elo.x, sU[2], ehi.y, elo.y, sU[5],
                          ehi.z, elo.z, sU[8], ehi.w, elo.w, sU[11]);

        float wd = (float)d + 35.0f * f0;
        float wh = (float)h + 35.0f * f1;
        float ww = (float)t + 35.0f * f2;

        unsigned rowoff = ((unsigned)d << 14) + ((unsigned)h << 7);

        // nearest-neighbor label for my own voxel (w = t)
        {
            unsigned nd = (unsigned)clamp127((int)rintf(wd));
            unsigned nh = (unsigned)clamp127((int)rintf(wh));
            unsigned nw = (unsigned)clamp127((int)rintf(ww));
            int lv = lblb[(nd << 14) + (nh << 7) + nw];
            __stcs(&outl[rowoff + (unsigned)t], (float)lv);
        }

        // target voxels' coords via exact register broadcast
        float wdA = __shfl_sync(FULL, wd, p);
        float whA = __shfl_sync(FULL, wh, p);
        float wwA = __shfl_sync(FULL, ww, p);
        float wdB = __shfl_sync(FULL, wd, 16 + p);
        float whB = __shfl_sync(FULL, wh, 16 + p);
        float wwB = __shfl_sync(FULL, ww, 16 + p);

        float4 pA = gather_half(img4, half, wdA, whA, wwA);
        float4 pB = gather_half(img4, half, wdB, whB, wwB);

        float4 send = half ? pA : pB;
        float4 recv;
        recv.x = __shfl_xor_sync(FULL, send.x, 1);
        recv.y = __shfl_xor_sync(FULL, send.y, 1);
        recv.z = __shfl_xor_sync(FULL, send.z, 1);
        recv.w = __shfl_xor_sync(FULL, send.w, 1);

        float4 mine = half ? pB : pA;
        float4 res;
        res.x = mine.x + recv.x;
        res.y = mine.y + recv.y;
        res.z = mine.z + recv.z;
        res.w = mine.w + recv.w;

        unsigned outw = (unsigned)(half ? vB : vA);
        __stcs(&outi4[rowoff + outw], res);
    }
}

extern "C" void kernel_launch(void* const* d_in, const int* in_sizes, int n_in,
                              void* d_out, int out_size) {
    const float* img = nullptr;
    const float* coarse = nullptr;
    const int*   lbl = nullptr;
    for (int i = 0; i < n_in; ++i) {
        if      (in_sizes[i] == IMG_ELEMS) img    = (const float*)d_in[i];
        else if (in_sizes[i] == 384)       coarse = (const float*)d_in[i];
        else if (in_sizes[i] == VOX)       lbl    = (const int*)d_in[i];
    }
    float* out = (float*)d_out;

    precompute_E_kernel<<<1, 512>>>();
    deform_kernel<<<BB * DD * 16, 128>>>(img, coarse, lbl, out);
}

// round 16
// speedup vs baseline: 1.0080x; 1.0080x over previous
#include <cuda_runtime.h>
#include <math.h>

// Problem constants (fixed shapes from setup_inputs)
#define BB   2
#define DD   128
#define HH   128
#define WW   128
#define IMG_ELEMS (BB*DD*HH*WW*4)    // 16777216
#define VOX       (BB*DD*HH*WW)      // 4194304

__device__ float g_Ehi[128 * 4];
__device__ float g_Elo[128 * 4];

// ---------------- double-float (two-float) arithmetic -----------------
struct df { float h, l; };

__device__ __forceinline__ df qts(float a, float b) {
    float s = a + b;
    return { s, b - (s - a) };
}
__device__ __forceinline__ df two_sum(float a, float b) {
    float s = a + b;
    float t = s - a;
    return { s, (a - (s - t)) + (b - t) };
}
__device__ __forceinline__ df two_prod(float a, float b) {
    float p = a * b;
    return { p, fmaf(a, b, -p) };
}
__device__ __forceinline__ df df_mul(df a, df b) {
    df p = two_prod(a.h, b.h);
    p.l = p.l + (a.h * b.l + a.l * b.h);
    return qts(p.h, p.l);
}
__device__ __forceinline__ df df_mul_f(df a, float b) {
    df p = two_prod(a.h, b);
    p.l = p.l + a.l * b;
    return qts(p.h, p.l);
}
__device__ __forceinline__ df df_add(df a, df b) {
    df s = two_sum(a.h, b.h);
    s.l = s.l + (a.l + b.l);
    return qts(s.h, s.l);
}
// -----------------------------------------------------------------------

// Cephes/Eigen-style vectorized expf (XLA:CPU) — VALIDATED, do not touch.
__device__ float cephes_expf(float x) {
    const float LOG2EF = 1.44269504088896341f;
    const float C1 = 0.693359375f;
    const float C2 = -2.12194440e-4f;
    float m = floorf(fmaf(x, LOG2EF, 0.5f));
    float r = fmaf(m, -C1, x);
    r = fmaf(m, -C2, r);
    float r2 = __fmul_rn(r, r);
    float y = 1.9875691500E-4f;
    y = fmaf(y, r, 1.3981999507E-3f);
    y = fmaf(y, r, 8.3334519073E-3f);
    y = fmaf(y, r, 4.1665795894E-2f);
    y = fmaf(y, r, 1.6666665459E-1f);
    y = fmaf(y, r, 5.0000001201E-1f);
    y = fmaf(y, r2, r);
    y = __fadd_rn(y, 1.0f);
    return ldexpf(y, (int)m);
}

// fp32 Keys cubic weight with separate roundings per op — VALIDATED.
__device__ float keys_f32_strict(float x) {
    float t1 = __fmul_rn(1.5f, x);
    float t2 = __fsub_rn(t1, 2.5f);
    float t3 = __fmul_rn(t2, x);
    float t4 = __fmul_rn(t3, x);
    float out = __fadd_rn(t4, 1.0f);
    if (x >= 1.0f) {
        float u1 = __fmul_rn(-0.5f, x);
        float u2 = __fadd_rn(u1, 2.5f);
        float u3 = __fmul_rn(u2, x);
        float u4 = __fsub_rn(u3, 4.0f);
        float u5 = __fmul_rn(u4, x);
        out = __fadd_rn(u5, 2.0f);
    }
    if (x >= 2.0f) out = 0.0f;
    return out;
}

// Every product and accumulation order IDENTICAL to validated version.
__global__ void precompute_E_kernel() {
    __shared__ float s_taps[16];
    __shared__ float s_Wn[128 * 4];

    int tid = threadIdx.x;
    if (tid >= 512) return;
    int p = tid >> 2, c = tid & 3;

    if (tid < 16) {
        float kf[16];
        float ksum = 0.0f;
        #pragma unroll
        for (int j = 0; j < 16; ++j) {
            float off = (float)(j - 7);
            float sq = __fmul_rn(off, off);
            float arg = -__fdiv_rn(sq, 12.5f);
            kf[j] = cephes_expf(arg);
            ksum = __fadd_rn(ksum, kf[j]);
        }
        s_taps[tid] = __fdiv_rn(kf[tid], ksum);
    }

    {
        float sf = __fsub_rn(__fmul_rn(__fadd_rn((float)p, 0.5f), 0.03125f), 0.5f);
        float wc[4];
        float ssum = 0.0f;
        #pragma unroll
        for (int cc = 0; cc < 4; ++cc) {
            float x = fabsf(__fsub_rn(sf, (float)cc));
            wc[cc] = keys_f32_strict(x);
            ssum = __fadd_rn(ssum, wc[cc]);
        }
        s_Wn[p * 4 + c] = __fdiv_rn(wc[c], ssum);
    }
    __syncthreads();

    double E = 0.0;
    #pragma unroll
    for (int j = 0; j < 16; ++j) {
        int q = p - 7 + j;
        if (q < 0 || q >= 128) continue;
        E += (double)s_taps[j] * (double)s_Wn[q * 4 + c];
    }
    float hi = (float)E;
    g_Ehi[p * 4 + c] = hi;
    g_Elo[p * 4 + c] = (float)(E - (double)hi);
}

__device__ __forceinline__ int clamp127(int v) {
    return min(max(v, 0), 127);
}

// Compensated (Dot2-style) 4-term df·df dot product — VALIDATED.
__device__ __forceinline__ float dot2_4(
    float eh0, float el0, df u0,
    float eh1, float el1, df u1,
    float eh2, float el2, df u2,
    float eh3, float el3, df u3)
{
    float s = __fmul_rn(eh0, u0.h);
    float c = fmaf(eh0, u0.h, -s);
    c = fmaf(eh0, u0.l, c);
    c = fmaf(el0, u0.h, c);
    #define DOT2_TERM(EH, EL, U)                         \
    {                                                    \
        float p_ = __fmul_rn(EH, (U).h);                 \
        float e_ = fmaf(EH, (U).h, -p_);                 \
        e_ = fmaf(EH, (U).l, e_);                        \
        e_ = fmaf(EL, (U).h, e_);                        \
        float t_ = s + p_;                               \
        float z_ = t_ - s;                               \
        float err_ = (s - (t_ - z_)) + (p_ - z_);        \
        s = t_;                                          \
        c = c + (e_ + err_);                             \
    }
    DOT2_TERM(eh1, el1, u1)
    DOT2_TERM(eh2, el2, u2)
    DOT2_TERM(eh3, el3, u3)
    #undef DOT2_TERM
    return s + c;
}

// Collapse one w-half of the trilinear stencil to a weighted float4 partial.
__device__ __forceinline__ float4 gather_half(
    const float4* __restrict__ img4, int half,
    float wd, float wh, float ww)
{
    float fld = floorf(wd), flh = floorf(wh), flw = floorf(ww);
    float td = wd - fld, th = wh - flh, tw = ww - flw;
    int i0d = (int)fld, i0h = (int)flh, i0w = (int)flw;
    unsigned d0 = (unsigned)clamp127(i0d), d1 = (unsigned)clamp127(i0d + 1);
    unsigned h0 = (unsigned)clamp127(i0h), h1 = (unsigned)clamp127(i0h + 1);
    unsigned wc = (unsigned)clamp127(i0w + half);
    float wwgt = half ? tw : (1.0f - tw);

    float4 c00 = img4[(d0 << 14) + (h0 << 7) + wc];
    float4 c01 = img4[(d0 << 14) + (h1 << 7) + wc];
    float4 c10 = img4[(d1 << 14) + (h0 << 7) + wc];
    float4 c11 = img4[(d1 << 14) + (h1 << 7) + wc];

    float omh = 1.0f - th, omd = 1.0f - td;
    float4 out;
    float a, bb;
    a = c00.x * omh + c01.x * th; bb = c10.x * omh + c11.x * th;
    out.x = (a * omd + bb * td) * wwgt;
    a = c00.y * omh + c01.y * th; bb = c10.y * omh + c11.y * th;
    out.y = (a * omd + bb * td) * wwgt;
    a = c00.z * omh + c01.z * th; bb = c10.z * omh + c11.z * th;
    out.z = (a * omd + bb * td) * wwgt;
    a = c00.w * omh + c01.w * th; bb = c10.w * omh + c11.w * th;
    out.w = (a * omd + bb * td) * wwgt;
    return out;
}

// Block = (b, d, h4): processes rows h = 4*h4 .. 4*h4+3.
__global__ void __launch_bounds__(128) deform_kernel(
    const float* __restrict__ img,     // [B,128,128,128,4]
    const float* __restrict__ coarse,  // [B,4,4,4,3]
    const int*   __restrict__ lbl,     // [B,128,128,128]
    float*       __restrict__ out)     // [IMG_ELEMS] image then [VOX] label
{
    __shared__ float  s_coarse[192];
    __shared__ df     s_prod[4 * 16];   // [row][k]
    __shared__ df     s_U[4 * 12];      // [row][cw*3+comp]

    int bid = blockIdx.x;
    int h4 = bid & 31;
    int d  = (bid >> 5) & 127;
    int b  = bid >> 12;
    int t  = threadIdx.x;
    int hbase = h4 << 2;

    for (int i = t; i < 192; i += 128) s_coarse[i] = coarse[b * 192 + i];
    if (t < 64) {
        int r  = t >> 4;
        int k  = t & 15;
        int cd = k >> 2, ch = k & 3;
        int h  = hbase + r;
        df Ed = { g_Ehi[d * 4 + cd], g_Elo[d * 4 + cd] };
        df Eh = { g_Ehi[h * 4 + ch], g_Elo[h * 4 + ch] };
        s_prod[r * 16 + k] = df_mul(Ed, Eh);
    }
    __syncthreads();

    if (t < 48) {
        int r  = t / 12;
        int u  = t - r * 12;
        int cw = u / 3, comp = u - cw * 3;
        df acc = { 0.f, 0.f };
        #pragma unroll
        for (int k = 0; k < 16; ++k)
            acc = df_add(acc, df_mul_f(s_prod[r * 16 + k],
                                       s_coarse[(k * 4 + cw) * 3 + comp]));
        s_U[r * 12 + u] = acc;
    }
    __syncthreads();

    // E row for w = t: loaded ONCE for all 4 rows.
    const float4 ehi = *reinterpret_cast<const float4*>(&g_Ehi[t * 4]);
    const float4 elo = *reinterpret_cast<const float4*>(&g_Elo[t * 4]);

    // per-batch base pointers
    const float4* __restrict__ img4  = reinterpret_cast<const float4*>(img) + (long)b * (128 * 128 * 128);
    const int*    __restrict__ lblb  = lbl + (long)b * (128 * 128 * 128);
    float4*       __restrict__ outi4 = reinterpret_cast<float4*>(out) + (long)b * (128 * 128 * 128);
    float*        __restrict__ outl  = out + IMG_ELEMS + (long)b * (128 * 128 * 128);

    int lane  = t & 31;
    int p     = lane >> 1;
    int half  = lane & 1;
    int wbase = t & ~31;
    int vA    = wbase + p;
    int vB    = wbase + 16 + p;
    const unsigned FULL = 0xffffffffu;

    // unroll 1: keep per-iteration live set minimal -> low regs, high occupancy.
    // (R12 established cross-row MLP buys nothing; the kernel is L1-throughput
    //  bound, so registers/occupancy are the binding resource.)
    #pragma unroll 1
    for (int r = 0; r < 4; ++r) {
        int h = hbase + r;
        const df* sU = &s_U[r * 12];

        // flow for w = t — identical math/order to validated rounds
        float f0 = dot2_4(ehi.x, elo.x, sU[0], ehi.y, elo.y, sU[3],
                          ehi.z, elo.z, sU[6], ehi.w, elo.w, sU[9]);
        float f1 = dot2_4(ehi.x, elo.x, sU[1], ehi.y, elo.y, sU[4],
                          ehi.z, elo.z, sU[7], ehi.w, elo.w, sU[10]);
        float f2 = dot2_4(ehi.x, elo.x, sU[2], ehi.y, elo.y, sU[5],
                          ehi.z, elo.z, sU[8], ehi.w, elo.w, sU[11]);

        float wd = (float)d + 35.0f * f0;
        float wh = (float)h + 35.0f * f1;
        float ww = (float)t + 35.0f * f2;

        unsigned rowoff = ((unsigned)d << 14) + ((unsigned)h << 7);

        // nearest-neighbor label for my own voxel (w = t)
        {
            unsigned nd = (unsigned)clamp127((int)rintf(wd));
            unsigned nh = (unsigned)clamp127((int)rintf(wh));
            unsigned nw = (unsigned)clamp127((int)rintf(ww));
            int lv = lblb[(nd << 14) + (nh << 7) + nw];
            __stcs(&outl[rowoff + (unsigned)t], (float)lv);
        }

        // target voxels' coords via exact register broadcast
        float wdA = __shfl_sync(FULL, wd, p);
        float whA = __shfl_sync(FULL, wh, p);
        float wwA = __shfl_sync(FULL, ww, p);
        float wdB = __shfl_sync(FULL, wd, 16 + p);
        float whB = __shfl_sync(FULL, wh, 16 + p);
        float wwB = __shfl_sync(FULL, ww, 16 + p);

        float4 pA = gather_half(img4, half, wdA, whA, wwA);
        float4 pB = gather_half(img4, half, wdB, whB, wwB);

        float4 send = half ? pA : pB;
        float4 recv;
        recv.x = __shfl_xor_sync(FULL, send.x, 1);
        recv.y = __shfl_xor_sync(FULL, send.y, 1);
        recv.z = __shfl_xor_sync(FULL, send.z, 1);
        recv.w = __shfl_xor_sync(FULL, send.w, 1);

        float4 mine = half ? pB : pA;
        float4 res;
        res.x = mine.x + recv.x;
        res.y = mine.y + recv.y;
        res.z = mine.z + recv.z;
        res.w = mine.w + recv.w;

        unsigned outw = (unsigned)(half ? vB : vA);
        __stcs(&outi4[rowoff + outw], res);
    }
}

extern "C" void kernel_launch(void* const* d_in, const int* in_sizes, int n_in,
                              void* d_out, int out_size) {
    const float* img = nullptr;
    const float* coarse = nullptr;
    const int*   lbl = nullptr;
    for (int i = 0; i < n_in; ++i) {
        if      (in_sizes[i] == IMG_ELEMS) img    = (const float*)d_in[i];
        else if (in_sizes[i] == 384)       coarse = (const float*)d_in[i];
        else if (in_sizes[i] == VOX)       lbl    = (const int*)d_in[i];
    }
    float* out = (float*)d_out;

    precompute_E_kernel<<<1, 512>>>();
    deform_kernel<<<BB * DD * 32, 128>>>(img, coarse, lbl, out);
}